// round 1
// baseline (speedup 1.0000x reference)
#include <cuda_runtime.h>
#include <math.h>

// B=32, N=256, D=256, H=8, K=16
#define BB 32
#define NN 256
#define DD 256
#define HH 8
#define KK 16

#define QOFF 16777216        // B*H*N*N
#define SCALAR_OFF 33554432  // 2*B*H*N*N
#define LOG_EPS -18.420680744f   // log(1e-8)

// scratch (device globals — no allocation allowed)
__device__ __align__(16) float d_Wt[512 * 16];   // W_eff transposed: [j][k]
__device__ __align__(16) float d_beff[16];
__device__ __align__(16) float d_S[BB * NN * KK];
__device__ __align__(16) float d_G[HH * KK * KK];
__device__ float d_greg;
__device__ float d_orth[BB];
__device__ float d_usage[BB];

// ---------------------------------------------------------------------------
// Kernel A: W_eff[k][j] = sum_d W_slot[k,d] * W_fusion[d,j]   (stored as Wt[j][k])
// grid 32 x 256: block pair covers one k (broadcast W_slot row in smem)
// ---------------------------------------------------------------------------
__global__ void k_weff(const float* __restrict__ Wslot,
                       const float* __restrict__ Wfus) {
    __shared__ float ws[256];
    int k = blockIdx.x >> 1;
    int j = ((blockIdx.x & 1) << 8) + threadIdx.x;
    ws[threadIdx.x] = Wslot[k * 256 + threadIdx.x];
    __syncthreads();
    float acc = 0.f;
#pragma unroll 8
    for (int d = 0; d < 256; ++d) acc += ws[d] * Wfus[d * 512 + j];
    d_Wt[j * 16 + k] = acc;
}

// ---------------------------------------------------------------------------
// Kernel B: G = sinkhorn(softmax(G_param)), zero diag, g_reg, b_eff.  1 block x 256.
// ---------------------------------------------------------------------------
__global__ void k_G(const float* __restrict__ Gp,
                    const float* __restrict__ Wslot,
                    const float* __restrict__ bfus,
                    const float* __restrict__ bslot) {
    __shared__ float g[2048];
    __shared__ float norms[8];
    __shared__ float red[8];
    int tid = threadIdx.x;

#pragma unroll
    for (int h = 0; h < 8; h++) g[h * 256 + tid] = Gp[h * 256 + tid];

    if (tid < 16) {  // b_eff = W_slot @ b_fusion + b_slot
        float s = bslot[tid];
        for (int d = 0; d < 256; ++d) s += Wslot[tid * 256 + d] * bfus[d];
        d_beff[tid] = s;
    }
    __syncthreads();

    // row softmax then clamp to 1e-6
    if (tid < 128) {
        int base = (tid >> 4) * 256 + (tid & 15) * 16;
        float m = -1e30f;
        for (int j = 0; j < 16; j++) m = fmaxf(m, g[base + j]);
        float e[16], s = 0.f;
        for (int j = 0; j < 16; j++) { e[j] = expf(g[base + j] - m); s += e[j]; }
        float inv = 1.f / s;
        for (int j = 0; j < 16; j++) g[base + j] = fmaxf(e[j] * inv, 1e-6f);
    }
    __syncthreads();

    // sinkhorn: 10 x (row-normalize, col-normalize)
    for (int it = 0; it < 10; ++it) {
        if (tid < 128) {
            int base = (tid >> 4) * 256 + (tid & 15) * 16;
            float s = 0.f;
            for (int j = 0; j < 16; j++) s += g[base + j];
            float inv = 1.f / (s + 1e-6f);
            for (int j = 0; j < 16; j++) g[base + j] *= inv;
        }
        __syncthreads();
        if (tid < 128) {
            int cb = (tid >> 4) * 256 + (tid & 15);
            float s = 0.f;
            for (int i = 0; i < 16; i++) s += g[cb + i * 16];
            float inv = 1.f / (s + 1e-6f);
            for (int i = 0; i < 16; i++) g[cb + i * 16] *= inv;
        }
        __syncthreads();
    }
    if (tid < 128) g[(tid >> 4) * 256 + (tid & 15) * 17] = 0.f;  // zero diag
    __syncthreads();

#pragma unroll
    for (int h = 0; h < 8; h++) d_G[h * 256 + tid] = g[h * 256 + tid];

    // g_reg = 0.02*(||sum_h V_h||^2 - H)/(H*(H-1)) with V_h normalized rows
    int w = tid >> 5, lane = tid & 31;
    float s = 0.f;
    for (int q = lane; q < 256; q += 32) { float v = g[w * 256 + q]; s += v * v; }
#pragma unroll
    for (int o = 16; o; o >>= 1) s += __shfl_xor_sync(0xffffffffu, s, o);
    if (lane == 0) norms[w] = fmaxf(sqrtf(s), 1e-8f);
    __syncthreads();
    float wv = 0.f;
#pragma unroll
    for (int h = 0; h < 8; h++) wv += g[h * 256 + tid] / norms[h];
    float sq = wv * wv;
#pragma unroll
    for (int o = 16; o; o >>= 1) sq += __shfl_xor_sync(0xffffffffu, sq, o);
    if (lane == 0) red[w] = sq;
    __syncthreads();
    if (tid == 0) {
        float t = 0.f;
        for (int i = 0; i < 8; i++) t += red[i];
        d_greg = 0.02f * (t - 8.0f) / 56.0f;
    }
}

// ---------------------------------------------------------------------------
// Kernel C: S = softmax(X @ W_eff^T + b_eff).  grid 256 x 256, warp-per-row.
// Wt in smem padded to stride 20 (conflict-free LDS.128 at 80B lane stride)
// ---------------------------------------------------------------------------
__global__ void __launch_bounds__(256) k_S(const float* __restrict__ desc,
                                           const float* __restrict__ nv) {
    __shared__ float Wt[512 * 20];
    __shared__ float be[16];
    int tid = threadIdx.x;
    const float4* src = (const float4*)d_Wt;
#pragma unroll
    for (int q = 0; q < 8; q++) {
        int idx = tid + q * 256;        // 2048 float4s
        float4 v = src[idx];
        int j = idx >> 2, c = idx & 3;
        *(float4*)&Wt[j * 20 + c * 4] = v;
    }
    if (tid < 16) be[tid] = d_beff[tid];
    __syncthreads();

    int warp = tid >> 5, lane = tid & 31;
    for (int rr = 0; rr < 4; ++rr) {
        int row = blockIdx.x * 32 + warp * 4 + rr;
        const float* xd = desc + row * 256;
        const float* xn = nv + row * 256;
        float acc[16];
#pragma unroll
        for (int k = 0; k < 16; k++) acc[k] = 0.f;
#pragma unroll
        for (int jj = 0; jj < 16; jj++) {
            int j = lane + jj * 32;
            float x = (jj < 8) ? xd[j] : xn[j - 256];
            const float* wp = &Wt[j * 20];
            float4 w0 = *(const float4*)(wp);
            float4 w1 = *(const float4*)(wp + 4);
            float4 w2 = *(const float4*)(wp + 8);
            float4 w3 = *(const float4*)(wp + 12);
            acc[0] += x * w0.x; acc[1] += x * w0.y; acc[2] += x * w0.z; acc[3] += x * w0.w;
            acc[4] += x * w1.x; acc[5] += x * w1.y; acc[6] += x * w1.z; acc[7] += x * w1.w;
            acc[8] += x * w2.x; acc[9] += x * w2.y; acc[10] += x * w2.z; acc[11] += x * w2.w;
            acc[12] += x * w3.x; acc[13] += x * w3.y; acc[14] += x * w3.z; acc[15] += x * w3.w;
        }
#pragma unroll
        for (int o = 16; o; o >>= 1)
#pragma unroll
            for (int k = 0; k < 16; k++)
                acc[k] += __shfl_xor_sync(0xffffffffu, acc[k], o);
        float m = -1e30f;
#pragma unroll
        for (int k = 0; k < 16; k++) { acc[k] += be[k]; m = fmaxf(m, acc[k]); }
        float s = 0.f;
#pragma unroll
        for (int k = 0; k < 16; k++) { acc[k] = __expf(acc[k] - m); s += acc[k]; }
        float inv = 1.f / s;
        float myv = 0.f;
#pragma unroll
        for (int k = 0; k < 16; k++)
            if (lane == k) myv = acc[k] * inv;
        if (lane < 16) d_S[row * 16 + lane] = myv;
    }
}

// ---------------------------------------------------------------------------
// Kernel D (dominant): per (b,h,row-chunk of 32): A = (2*S G) S^T, row softmax,
// write Q and bias_log. grid = B*H*8 = 2048 blocks x 256 threads.
// Warp processes 4 rows (2 pairs of 2 for S-tile register reuse).
// ---------------------------------------------------------------------------
__global__ void __launch_bounds__(256) k_Q(float* __restrict__ out) {
    __shared__ float Ss[256 * 20];
    __shared__ float Gs[256];
    __shared__ float SGs[32 * 16];
    int tid = threadIdx.x;
    int bh = blockIdx.x >> 3;
    int chunk = blockIdx.x & 7;
    int b = bh >> 3, h = bh & 7;

    const float4* sp = (const float4*)(d_S + b * 4096);
#pragma unroll
    for (int q = 0; q < 4; q++) {
        float4 v = sp[tid * 4 + q];
        *(float4*)&Ss[tid * 20 + q * 4] = v;   // row tid, chunk q
    }
    Gs[tid] = d_G[h * 256 + tid];
    __syncthreads();

    // SG for this block's 32 rows, pre-scaled by 1/tau = 2
#pragma unroll
    for (int r = 0; r < 2; r++) {
        int e = tid + r * 256;
        int nl = e >> 4, l = e & 15;
        int n = chunk * 32 + nl;
        const float* srow = &Ss[n * 20];
        float s = 0.f;
#pragma unroll
        for (int k = 0; k < 16; k++) s += srow[k] * Gs[k * 16 + l];
        SGs[nl * 16 + l] = 2.0f * s;
    }
    __syncthreads();

    int warp = tid >> 5, lane = tid & 31;
    int n0loc = warp * 4;
#pragma unroll
    for (int p = 0; p < 2; p++) {
        int ra = n0loc + p * 2, rb = ra + 1;
        float sg0[16], sg1[16];
#pragma unroll
        for (int l = 0; l < 16; l++) { sg0[l] = SGs[ra * 16 + l]; sg1[l] = SGs[rb * 16 + l]; }
        float a0[8], a1[8];
#pragma unroll
        for (int c = 0; c < 8; c++) { a0[c] = 0.f; a1[c] = 0.f; }
#pragma unroll
        for (int c = 0; c < 8; c++) {
            int m = lane + c * 32;
            const float* srow = &Ss[m * 20];
            float sv[16];
            *(float4*)&sv[0]  = *(const float4*)(srow);
            *(float4*)&sv[4]  = *(const float4*)(srow + 4);
            *(float4*)&sv[8]  = *(const float4*)(srow + 8);
            *(float4*)&sv[12] = *(const float4*)(srow + 12);
#pragma unroll
            for (int l = 0; l < 16; l++) {
                a0[c] += sg0[l] * sv[l];
                a1[c] += sg1[l] * sv[l];
            }
        }
        // softmax + stores for the 2 rows
#pragma unroll
        for (int rr = 0; rr < 2; rr++) {
            float* a = rr ? a1 : a0;
            int nglob = bh * 256 + chunk * 32 + (rr ? rb : ra);
            float mx = a[0];
#pragma unroll
            for (int c = 1; c < 8; c++) mx = fmaxf(mx, a[c]);
#pragma unroll
            for (int o = 16; o; o >>= 1)
                mx = fmaxf(mx, __shfl_xor_sync(0xffffffffu, mx, o));
            float e[8], s = 0.f;
#pragma unroll
            for (int c = 0; c < 8; c++) { e[c] = __expf(a[c] - mx); s += e[c]; }
#pragma unroll
            for (int o = 16; o; o >>= 1) s += __shfl_xor_sync(0xffffffffu, s, o);
            float inv = 1.f / s;
            float lz = logf(s);
            float* bp = out + (size_t)nglob * 256;          // bias_log
            float* qp = out + QOFF + (size_t)nglob * 256;   // Q
#pragma unroll
            for (int c = 0; c < 8; c++) {
                int m = lane + c * 32;
                qp[m] = e[c] * inv;
                bp[m] = fmaxf(a[c] - mx - lz, LOG_EPS);
            }
        }
    }
}

// ---------------------------------------------------------------------------
// Kernel E: per-batch regularizer partials (deterministic, no atomics).
// grid 32 x 256.
// ---------------------------------------------------------------------------
__global__ void k_reg() {
    __shared__ float Ss[4096];
    __shared__ float red[8];
    __shared__ float us[16];
    int b = blockIdx.x, tid = threadIdx.x;
    const float4* sp = (const float4*)(d_S + b * 4096);
#pragma unroll
    for (int q = 0; q < 4; q++) ((float4*)Ss)[tid + q * 256] = sp[tid + q * 256];
    __syncthreads();

    int k = tid >> 4, l = tid & 15;
    float a = 0.f;
    for (int n = 0; n < 256; n++) a += Ss[n * 16 + k] * Ss[n * 16 + l];
    a *= (1.0f / 256.f);
    float off = (k != l) ? a : 0.f;
    float sq = off * off;
#pragma unroll
    for (int o = 16; o; o >>= 1) sq += __shfl_xor_sync(0xffffffffu, sq, o);
    if ((tid & 31) == 0) red[tid >> 5] = sq;

    if (tid < 16) {
        float u = 0.f;
        for (int n = 0; n < 256; n++) u += Ss[n * 16 + tid];
        us[tid] = u * (1.0f / 256.f);
    }
    __syncthreads();
    if (tid == 0) {
        float t = 0.f;
        for (int i = 0; i < 8; i++) t += red[i];
        d_orth[b] = 0.1f * t / 8192.0f;   // 0.1 * sum/(B*K*K), summed over b later
        float usum = 0.f;
        for (int kk = 0; kk < 16; kk++) usum += us[kk];
        float lK = logf(1.0f / 16.0f);
        float kl = 0.f;
        for (int kk = 0; kk < 16; kk++) {
            float uc = fmaxf(us[kk] / (usum + 1e-8f), 1e-8f);
            kl += uc * (logf(uc) - lK);
        }
        d_usage[b] = 0.1f * kl / 32.0f;
    }
}

__global__ void k_final(float* __restrict__ out) {
    if (threadIdx.x == 0) {
        float t = d_greg;
        for (int b = 0; b < 32; b++) t += d_orth[b];
        for (int b = 0; b < 32; b++) t += d_usage[b];
        out[SCALAR_OFF] = t;
    }
}

// ---------------------------------------------------------------------------
extern "C" void kernel_launch(void* const* d_in, const int* in_sizes, int n_in,
                              void* d_out, int out_size) {
    const float* desc  = (const float*)d_in[0];
    const float* nv    = (const float*)d_in[1];
    const float* Wfus  = (const float*)d_in[2];
    const float* bfus  = (const float*)d_in[3];
    const float* Wslot = (const float*)d_in[4];
    const float* bslot = (const float*)d_in[5];
    const float* Gp    = (const float*)d_in[6];
    float* out = (float*)d_out;

    k_weff<<<32, 256>>>(Wslot, Wfus);
    k_G<<<1, 256>>>(Gp, Wslot, bfus, bslot);
    k_S<<<256, 256>>>(desc, nv);
    k_Q<<<BB * HH * 8, 256>>>(out);
    k_reg<<<BB, 256>>>();
    k_final<<<1, 32>>>(out);
}